// round 5
// baseline (speedup 1.0000x reference)
#include <cuda_runtime.h>
#include <stdint.h>

#define NUM_BINS 256
#define NCH 48                       // B*C = 16*3
#define NPIX (1024 * 1024)           // H*W per channel
#define N4 (NPIX / 4)                // 262144 uchar4/float4 groups per channel
#define BLK_PER_CH 32
#define THREADS 256
#define CH_THREADS (BLK_PER_CH * THREADS)   // 8192
#define ITERS (N4 / CH_THREADS)             // exactly 32
#define REP 16                               // LUT replication factor

// Scratch (device globals — allocation-free, zero-initialized at module load)
__device__ int           g_hist[NCH * NUM_BINS];
__device__ float         g_cdf[NCH * NUM_BINS];
__device__ unsigned char g_bins[(size_t)NCH * NPIX];   // 48 MiB

__device__ __forceinline__ int quant(float v) {
    int q = (int)(fminf(fmaxf(v, 0.0f), 1.0f) * 255.0f);
    return min(max(q, 0), 255);
}

// ---------------------------------------------------------------------------
// Kernel 1: per-channel histogram (per-warp privatized) + quantized-bin store
//   grid = (BLK_PER_CH, NCH), block = 256        [unchanged: 42.8 µs, 69% DRAM]
// ---------------------------------------------------------------------------
__global__ void __launch_bounds__(THREADS) hist_kernel(const float* __restrict__ x) {
    __shared__ int sh[8 * NUM_BINS];            // 8 warps x 256 bins = 8 KB
    const int c    = blockIdx.y;
    const int warp = threadIdx.x >> 5;
    int* swh = &sh[warp * NUM_BINS];

    #pragma unroll
    for (int i = threadIdx.x; i < 8 * NUM_BINS; i += THREADS) sh[i] = 0;
    __syncthreads();

    const float4* xc = reinterpret_cast<const float4*>(x + (size_t)c * NPIX);
    uchar4*       bc = reinterpret_cast<uchar4*>(g_bins + (size_t)c * NPIX);

    const int base = blockIdx.x * THREADS + threadIdx.x;
    #pragma unroll 2
    for (int k = 0; k < ITERS; k++) {
        int i = base + k * CH_THREADS;
        float4 v = xc[i];
        int q0 = quant(v.x), q1 = quant(v.y), q2 = quant(v.z), q3 = quant(v.w);

        atomicAdd(&swh[q0], 1);
        atomicAdd(&swh[q1], 1);
        atomicAdd(&swh[q2], 1);
        atomicAdd(&swh[q3], 1);

        bc[i] = make_uchar4((unsigned char)q0, (unsigned char)q1,
                            (unsigned char)q2, (unsigned char)q3);
    }
    __syncthreads();

    int bin = threadIdx.x;
    int sum = 0;
    #pragma unroll
    for (int w = 0; w < 8; w++) sum += sh[w * NUM_BINS + bin];
    if (sum) atomicAdd(&g_hist[c * NUM_BINS + bin], sum);
}

// ---------------------------------------------------------------------------
// Kernel 2: CDF scan + normalize, then re-zero g_hist for the next replay
//   grid = NCH, block = 256                       [unchanged]
// ---------------------------------------------------------------------------
__global__ void cdf_kernel() {
    __shared__ float s[NUM_BINS];
    const int c = blockIdx.x;
    const int t = threadIdx.x;

    s[t] = (float)g_hist[c * NUM_BINS + t];
    g_hist[c * NUM_BINS + t] = 0;       // restore zero-invariant for next call
    __syncthreads();

    #pragma unroll
    for (int off = 1; off < NUM_BINS; off <<= 1) {
        float v = (t >= off) ? s[t - off] : 0.0f;
        __syncthreads();
        s[t] += v;
        __syncthreads();
    }

    float total = s[NUM_BINS - 1];
    g_cdf[c * NUM_BINS + t] = s[t] / fmaxf(total, 1.0f);
}

// ---------------------------------------------------------------------------
// Kernel 3: remap — grid-stride uchar4 (R1 shape) with a 16-way replicated,
//           conflict-free LUT: lookup srep[bin*16 + (lane&15)] (≤2-way),
//           init strided so STS is conflict-free (R2's bug fixed).
//   grid = (24, NCH), block = 256, smem = 16 KB
// ---------------------------------------------------------------------------
__global__ void __launch_bounds__(THREADS) remap_kernel(float* __restrict__ out) {
    __shared__ float srep[NUM_BINS * REP];      // 16 KB
    const int c    = blockIdx.y;
    const int half = threadIdx.x & (REP - 1);   // lane & 15

    // conflict-free init: consecutive threads -> consecutive smem words;
    // value = cdf[idx / REP] (broadcast-friendly LDG, L1/L2 hot)
    #pragma unroll
    for (int idx = threadIdx.x; idx < NUM_BINS * REP; idx += THREADS)
        srep[idx] = g_cdf[c * NUM_BINS + (idx >> 4)];
    __syncthreads();

    const uchar4* bc = reinterpret_cast<const uchar4*>(g_bins + (size_t)c * NPIX);
    float4*       oc = reinterpret_cast<float4*>(out + (size_t)c * NPIX);

    const int stride = gridDim.x * blockDim.x;          // 6144
    for (int i = blockIdx.x * blockDim.x + threadIdx.x; i < N4; i += stride) {
        uchar4 q = bc[i];
        float4 r;
        r.x = srep[((int)q.x << 4) + half];
        r.y = srep[((int)q.y << 4) + half];
        r.z = srep[((int)q.z << 4) + half];
        r.w = srep[((int)q.w << 4) + half];
        oc[i] = r;
    }
}

// ---------------------------------------------------------------------------
extern "C" void kernel_launch(void* const* d_in, const int* in_sizes, int n_in,
                              void* d_out, int out_size) {
    const float* x   = (const float*)d_in[0];
    float*       out = (float*)d_out;

    dim3 gridH(BLK_PER_CH, NCH);    // 1536 CTAs
    hist_kernel<<<gridH, THREADS>>>(x);
    cdf_kernel<<<NCH, NUM_BINS>>>();
    dim3 gridR(24, NCH);            // 1152 CTAs
    remap_kernel<<<gridR, THREADS>>>(out);
}

// round 6
// speedup vs baseline: 1.0631x; 1.0631x over previous
#include <cuda_runtime.h>
#include <stdint.h>

#define NUM_BINS 256
#define NCH 48                       // B*C = 16*3
#define NPIX (1024 * 1024)           // H*W per channel
#define N4 (NPIX / 4)                // 262144 uchar4/float4 groups per channel
#define NQ (N4 / 4)                  // 65536 per quarter-stream
#define BLK_PER_CH 32
#define THREADS 256
#define CH_THREADS (BLK_PER_CH * THREADS)   // 8192
#define ITERS (N4 / CH_THREADS)             // exactly 32

// Scratch (device globals — allocation-free, zero-initialized at module load)
__device__ int           g_hist[NCH * NUM_BINS];
__device__ float         g_cdf[NCH * NUM_BINS];
__device__ unsigned char g_bins[(size_t)NCH * NPIX];   // 48 MiB

__device__ __forceinline__ int quant(float v) {
    // clamp01 then *255 then trunc: result is already in [0,255]
    return (int)(fminf(fmaxf(v, 0.0f), 1.0f) * 255.0f);
}

// ---------------------------------------------------------------------------
// Kernel 1: per-channel histogram (per-warp privatized) + quantized-bin store
//   grid = (BLK_PER_CH, NCH), block = 256
//   x is read streaming (__ldcs) so it doesn't evict g_bins from L2.
// ---------------------------------------------------------------------------
__global__ void __launch_bounds__(THREADS) hist_kernel(const float* __restrict__ x) {
    __shared__ int sh[8 * NUM_BINS];            // 8 warps x 256 bins = 8 KB
    const int c    = blockIdx.y;
    const int warp = threadIdx.x >> 5;
    int* swh = &sh[warp * NUM_BINS];

    #pragma unroll
    for (int i = threadIdx.x; i < 8 * NUM_BINS; i += THREADS) sh[i] = 0;
    __syncthreads();

    const float4* xc = reinterpret_cast<const float4*>(x + (size_t)c * NPIX);
    uchar4*       bc = reinterpret_cast<uchar4*>(g_bins + (size_t)c * NPIX);

    const int base = blockIdx.x * THREADS + threadIdx.x;
    #pragma unroll 2
    for (int k = 0; k < ITERS; k++) {
        int i = base + k * CH_THREADS;
        float4 v = __ldcs(&xc[i]);              // streaming read, evict-first
        int q0 = quant(v.x), q1 = quant(v.y), q2 = quant(v.z), q3 = quant(v.w);

        atomicAdd(&swh[q0], 1);
        atomicAdd(&swh[q1], 1);
        atomicAdd(&swh[q2], 1);
        atomicAdd(&swh[q3], 1);

        bc[i] = make_uchar4((unsigned char)q0, (unsigned char)q1,
                            (unsigned char)q2, (unsigned char)q3);
    }
    __syncthreads();

    int bin = threadIdx.x;
    int sum = 0;
    #pragma unroll
    for (int w = 0; w < 8; w++) sum += sh[w * NUM_BINS + bin];
    if (sum) atomicAdd(&g_hist[c * NUM_BINS + bin], sum);
}

// ---------------------------------------------------------------------------
// Kernel 2: CDF scan + normalize, then re-zero g_hist for the next replay
//   grid = NCH, block = 256                       [unchanged]
// ---------------------------------------------------------------------------
__global__ void cdf_kernel() {
    __shared__ float s[NUM_BINS];
    const int c = blockIdx.x;
    const int t = threadIdx.x;

    s[t] = (float)g_hist[c * NUM_BINS + t];
    g_hist[c * NUM_BINS + t] = 0;       // restore zero-invariant for next call
    __syncthreads();

    #pragma unroll
    for (int off = 1; off < NUM_BINS; off <<= 1) {
        float v = (t >= off) ? s[t - off] : 0.0f;
        __syncthreads();
        s[t] += v;
        __syncthreads();
    }

    float total = s[NUM_BINS - 1];
    g_cdf[c * NUM_BINS + t] = s[t] / fmaxf(total, 1.0f);
}

// ---------------------------------------------------------------------------
// Kernel 3: remap — plain 1 KB LUT (the only shape that measured well),
//           but 4 independent quarter-streams per thread for MLP_p1 = 4.
//           Output stored streaming (__stcs).
//   grid = (24, NCH), block = 256
// ---------------------------------------------------------------------------
__global__ void __launch_bounds__(THREADS) remap_kernel(float* __restrict__ out) {
    __shared__ float scdf[NUM_BINS];
    const int c = blockIdx.y;

    scdf[threadIdx.x] = g_cdf[c * NUM_BINS + threadIdx.x];
    __syncthreads();

    const uchar4* bc = reinterpret_cast<const uchar4*>(g_bins + (size_t)c * NPIX);
    float4*       oc = reinterpret_cast<float4*>(out + (size_t)c * NPIX);

    const int stride = gridDim.x * blockDim.x;          // 6144
    for (int i = blockIdx.x * blockDim.x + threadIdx.x; i < NQ; i += stride) {
        // 4 independent loads issued back-to-back (front-batched)
        uchar4 qa = bc[i];
        uchar4 qb = bc[i + NQ];
        uchar4 qc = bc[i + 2 * NQ];
        uchar4 qd = bc[i + 3 * NQ];

        float4 ra, rb, rc, rd;
        ra.x = scdf[qa.x]; ra.y = scdf[qa.y]; ra.z = scdf[qa.z]; ra.w = scdf[qa.w];
        rb.x = scdf[qb.x]; rb.y = scdf[qb.y]; rb.z = scdf[qb.z]; rb.w = scdf[qb.w];
        rc.x = scdf[qc.x]; rc.y = scdf[qc.y]; rc.z = scdf[qc.z]; rc.w = scdf[qc.w];
        rd.x = scdf[qd.x]; rd.y = scdf[qd.y]; rd.z = scdf[qd.z]; rd.w = scdf[qd.w];

        __stcs(&oc[i],          ra);
        __stcs(&oc[i + NQ],     rb);
        __stcs(&oc[i + 2 * NQ], rc);
        __stcs(&oc[i + 3 * NQ], rd);
    }
}

// ---------------------------------------------------------------------------
extern "C" void kernel_launch(void* const* d_in, const int* in_sizes, int n_in,
                              void* d_out, int out_size) {
    const float* x   = (const float*)d_in[0];
    float*       out = (float*)d_out;

    dim3 gridH(BLK_PER_CH, NCH);    // 1536 CTAs
    hist_kernel<<<gridH, THREADS>>>(x);
    cdf_kernel<<<NCH, NUM_BINS>>>();
    dim3 gridR(24, NCH);            // 1152 CTAs
    remap_kernel<<<gridR, THREADS>>>(out);
}